// round 4
// baseline (speedup 1.0000x reference)
#include <cuda_runtime.h>

// DropBlock fused single kernel:
//   out = x * block_mask[h,w] * (3136 / sum(block_mask))
//   block_mask = 1 - backward_7x7_max_dilate(u < GAMMA)
//   GAMMA = 0.1/49 * (56^2/50^2) = 0.00256 exactly.
//
// Every CTA recomputes the mask from u (bit-parallel separable dilation).
// R3 fix: removed the divergent __shfl_down_sync under `if (tid < 56)`
// (lanes 56-63 of warp 1 never reached the full-mask shuffle -> deadlock).
// Popcounts go to shared; thread 0 sums 56 ints (negligible one-time cost).

#define H 56
#define W 56
#define HW 3136          // 56*56
#define HW4 784          // HW/4
#define GAMMA 0.00256f
#define V4_PER_THREAD 16
#define THREADS 256
#define V4_PER_CTA (THREADS * V4_PER_THREAD)   // 4096

__global__ void __launch_bounds__(THREADS) dropblock_kernel(
    const float4* __restrict__ x, const float* __restrict__ u,
    float4* __restrict__ out) {
    __shared__ float su[H * 57];                 // stride-57 pad: conflict-free row reads
    __shared__ unsigned long long rowd[H];
    __shared__ unsigned long long dil[H];
    __shared__ int pc[H];
    __shared__ float4 sm4[HW4];                  // mask * scale, float4-packed
    __shared__ float s_scale;

    const int tid = threadIdx.x;

    // ── Phase 1a: coalesced load of u into padded shared ──
    #pragma unroll
    for (int j = 0; j < 13; ++j) {
        const int s = tid + j * THREADS;
        if (s < HW) su[(s / W) * 57 + (s % W)] = u[s];
    }
    __syncthreads();

    // ── Phase 1b: row-wise backward dilation (width 7) as bit ops ──
    if (tid < H) {
        unsigned long long s = 0ULL;
        #pragma unroll
        for (int w = 0; w < W; ++w)
            s |= (unsigned long long)(su[tid * 57 + w] < GAMMA) << w;
        unsigned long long a = s | (s << 1);     // shifts {0,1}
        unsigned long long b = a | (a << 2);     // shifts {0..3}
        unsigned long long c = b | (b << 3);     // shifts {0..6}
        rowd[tid] = c & ((1ULL << W) - 1ULL);
    }
    __syncthreads();

    // ── Phase 1c: column-wise rolling OR over rows h-6..h + popcount ──
    if (tid < H) {
        const int h0 = tid - 6 < 0 ? 0 : tid - 6;
        unsigned long long d = 0ULL;
        for (int h = h0; h <= tid; ++h) d |= rowd[h];
        dil[tid] = d;
        pc[tid] = __popcll(d);
    }
    __syncthreads();

    // ── Phase 1d: thread 0 sums 56 popcounts; broadcast scale ──
    if (tid == 0) {
        int tot = 0;
        #pragma unroll
        for (int h = 0; h < H; ++h) tot += pc[h];
        s_scale = (float)HW / (float)(HW - tot);
    }
    __syncthreads();

    // ── Phase 1e: materialize mask*scale as float4[784] in shared ──
    const float scale = s_scale;
    #pragma unroll
    for (int j = 0; j < 4; ++j) {
        const int s4 = tid + j * THREADS;
        if (s4 < HW4) {
            const int h = s4 / 14;               // 14 float4 per row
            const int w0 = (s4 % 14) * 4;
            const unsigned long long bits = dil[h] >> w0;
            float4 mk;
            mk.x = (bits & 1ULL) ? 0.0f : scale;
            mk.y = (bits & 2ULL) ? 0.0f : scale;
            mk.z = (bits & 4ULL) ? 0.0f : scale;
            mk.w = (bits & 8ULL) ? 0.0f : scale;
            sm4[s4] = mk;
        }
    }
    __syncthreads();

    // ── Phase 2: streaming apply, 16 float4s per thread ──
    const int base = blockIdx.x * V4_PER_CTA + tid;
    #pragma unroll 4
    for (int k = 0; k < V4_PER_THREAD; ++k) {
        const int i = base + k * THREADS;
        const float4 mk = sm4[i % HW4];
        float4 v = __ldcs(&x[i]);
        v.x *= mk.x; v.y *= mk.y; v.z *= mk.z; v.w *= mk.w;
        __stcs(&out[i], v);
    }
}

extern "C" void kernel_launch(void* const* d_in, const int* in_sizes, int n_in,
                              void* d_out, int out_size) {
    const float* x = (const float*)d_in[0];   // (32,256,56,56) f32
    const float* u = (const float*)d_in[1];   // (56,56) f32

    // 32*256*3136 floats = 6,422,528 float4 = 1568 CTAs * 256 thr * 16
    const int n4 = out_size / 4;
    dropblock_kernel<<<n4 / V4_PER_CTA, THREADS>>>(
        (const float4*)x, u, (float4*)d_out);
}

// round 5
// speedup vs baseline: 1.2194x; 1.2194x over previous
#include <cuda_runtime.h>

// DropBlock, 2 kernels + PDL overlap:
//   mask_kernel: bit-parallel separable 7x7 backward dilation of (u < GAMMA),
//                writes mask*scale to g_ms4, triggers programmatic completion.
//   apply_kernel: launched with programmatic stream serialization; prefetches
//                its 4 float4s of x BEFORE cudaGridDependencySynchronize(),
//                overlapping its launch + first-load latency with mask_kernel.
// GAMMA = 0.1/49 * (56^2/50^2) = 0.00256 exactly.

#define H 56
#define W 56
#define HW 3136          // 56*56
#define HW4 784          // HW/4
#define GAMMA 0.00256f
#define THREADS 256
#define V4_PER_THREAD 4
#define V4_PER_CTA (THREADS * V4_PER_THREAD)   // 1024

// mask * scale, packed for float4 loads (12.5 KB, L1/L2 resident)
__device__ float4 g_ms4[HW4];

__global__ void __launch_bounds__(256) mask_kernel(const float* __restrict__ u) {
    __shared__ float su[H * 57];           // stride-57 pad
    __shared__ unsigned long long rowd[H];
    __shared__ unsigned long long dil[H];
    __shared__ int pc[H];
    __shared__ float s_scale;
    const int tid = threadIdx.x;

    // coalesced load of u into padded shared
    #pragma unroll
    for (int j = 0; j < 13; ++j) {
        const int s = tid + j * 256;
        if (s < HW) su[(s / W) * 57 + (s % W)] = u[s];
    }
    __syncthreads();

    // row-wise backward dilation (width 7) as bit ops
    if (tid < H) {
        unsigned long long s = 0ULL;
        #pragma unroll
        for (int w = 0; w < W; ++w)
            s |= (unsigned long long)(su[tid * 57 + w] < GAMMA) << w;
        unsigned long long a = s | (s << 1);     // {0,1}
        unsigned long long b = a | (a << 2);     // {0..3}
        unsigned long long c = b | (b << 3);     // {0..6}
        rowd[tid] = c & ((1ULL << W) - 1ULL);
    }
    __syncthreads();

    // column-wise rolling OR over rows h-6..h + popcount
    if (tid < H) {
        const int h0 = tid - 6 < 0 ? 0 : tid - 6;
        unsigned long long d = 0ULL;
        for (int h = h0; h <= tid; ++h) d |= rowd[h];
        dil[tid] = d;
        pc[tid] = __popcll(d);
    }
    __syncthreads();

    if (tid == 0) {
        int tot = 0;
        #pragma unroll
        for (int h = 0; h < H; ++h) tot += pc[h];
        s_scale = (float)HW / (float)(HW - tot);
    }
    __syncthreads();

    // write mask*scale as float4-packed floats
    const float scale = s_scale;
    float* ms = (float*)g_ms4;
    #pragma unroll
    for (int j = 0; j < 13; ++j) {
        const int s = tid + j * 256;
        if (s < HW)
            ms[s] = ((dil[s / W] >> (s % W)) & 1ULL) ? 0.0f : scale;
    }
    __threadfence();
    __syncthreads();
    cudaTriggerProgrammaticLaunchCompletion();
}

__global__ void __launch_bounds__(THREADS) apply_kernel(
    const float4* __restrict__ x, float4* __restrict__ out) {
    const int base = blockIdx.x * V4_PER_CTA + threadIdx.x;

    // prefetch x before depending on mask_kernel's output
    float4 v[V4_PER_THREAD];
    #pragma unroll
    for (int k = 0; k < V4_PER_THREAD; ++k)
        v[k] = __ldcs(&x[base + k * THREADS]);

    cudaGridDependencySynchronize();

    #pragma unroll
    for (int k = 0; k < V4_PER_THREAD; ++k) {
        const int i = base + k * THREADS;
        const float4 mk = g_ms4[i % HW4];
        v[k].x *= mk.x; v[k].y *= mk.y; v[k].z *= mk.z; v[k].w *= mk.w;
        __stcs(&out[i], v[k]);
    }
}

extern "C" void kernel_launch(void* const* d_in, const int* in_sizes, int n_in,
                              void* d_out, int out_size) {
    const float* x = (const float*)d_in[0];   // (32,256,56,56) f32
    const float* u = (const float*)d_in[1];   // (56,56) f32

    mask_kernel<<<1, 256>>>(u);

    // 6,422,528 float4 = 6272 CTAs * 256 thr * 4
    const int n4 = out_size / 4;

    cudaLaunchConfig_t cfg = {};
    cfg.gridDim = dim3(n4 / V4_PER_CTA, 1, 1);
    cfg.blockDim = dim3(THREADS, 1, 1);
    cfg.dynamicSmemBytes = 0;
    cfg.stream = 0;
    cudaLaunchAttribute attr[1];
    attr[0].id = cudaLaunchAttributeProgrammaticStreamSerialization;
    attr[0].val.programmaticStreamSerializationAllowed = 1;
    cfg.attrs = attr;
    cfg.numAttrs = 1;
    cudaLaunchKernelEx(&cfg, apply_kernel, (const float4*)x, (float4*)d_out);
}